// round 13
// baseline (speedup 1.0000x reference)
#include <cuda_runtime.h>
#include <cuda_fp16.h>
#include <cstdint>
#include <cstddef>

// Problem constants
constexpr int BATCH = 128;
constexpr int CMAX  = 272;
constexpr int TLEN  = 512;
constexpr int D1    = 320;
constexpr int NSUBJ = 8;
constexpr int CPAD  = 288;   // 9 * 32 channels (zero-padded)
constexpr int DPAD  = 384;   // 3 * 128 d-rows (zero-padded)

// fp16 scratch (converted once per call in a pre-pass)
__device__ __align__(16) __half Xh[(size_t)BATCH * CPAD * TLEN];  // 37.7 MB
__device__ __align__(16) __half Wh[(size_t)NSUBJ * DPAD * CPAD];  // 1.8 MB

// ---------------- pre-convert kernel ----------------
constexpr int64_t NXV = (int64_t)BATCH * CPAD * TLEN / 8;
constexpr int64_t NWV = (int64_t)NSUBJ * DPAD * CPAD / 8;

__global__ __launch_bounds__(256)
void convert_kernel(const float* __restrict__ X, const float* __restrict__ W)
{
    const int64_t i = (int64_t)blockIdx.x * blockDim.x + threadIdx.x;
    if (i < NXV) {
        const int64_t h0 = i * 8;
        const int b   = (int)(h0 / ((int64_t)CPAD * TLEN));
        const int rem = (int)(h0 % ((int64_t)CPAD * TLEN));
        const int c   = rem / TLEN;
        const int t   = rem % TLEN;
        __half2 o[4] = {};
        if (c < CMAX) {
            const float4* src = reinterpret_cast<const float4*>(
                X + ((int64_t)b * CMAX + c) * TLEN + t);
            float4 v0 = src[0], v1 = src[1];
            o[0] = __floats2half2_rn(v0.x, v0.y);
            o[1] = __floats2half2_rn(v0.z, v0.w);
            o[2] = __floats2half2_rn(v1.x, v1.y);
            o[3] = __floats2half2_rn(v1.z, v1.w);
        }
        *reinterpret_cast<uint4*>(&Xh[h0]) = *reinterpret_cast<const uint4*>(o);
    } else if (i < NXV + NWV) {
        const int64_t h0 = (i - NXV) * 8;
        const int sd = (int)(h0 / CPAD);
        const int c  = (int)(h0 % CPAD);   // multiple of 8
        const int s  = sd / DPAD;
        const int d  = sd % DPAD;
        __half2 o[4] = {};
        if (d < D1 && c < CMAX) {
            const float4* src = reinterpret_cast<const float4*>(
                W + ((int64_t)s * D1 + d) * CMAX + c);
            float4 v0 = src[0], v1 = src[1];
            o[0] = __floats2half2_rn(v0.x, v0.y);
            o[1] = __floats2half2_rn(v0.z, v0.w);
            o[2] = __floats2half2_rn(v1.x, v1.y);
            o[3] = __floats2half2_rn(v1.z, v1.w);
        }
        *reinterpret_cast<uint4*>(&Wh[h0]) = *reinterpret_cast<const uint4*>(o);
    }
}

// ---------------- GEMM kernel: 128x128 CTA, 4 warps of 64x64 ----------------
constexpr int BM = 128;
constexpr int BN = 128;
constexpr int BK = 32;
constexpr int STAGES = 3;
constexpr int NIT = CPAD / BK;           // 9
constexpr int STAGE_BYTES = 16384;       // A 8KB + B 8KB
constexpr int SMEM_BYTES = STAGES * STAGE_BYTES;   // 49152

// Swizzled tile offsets (bytes). A: [m][k32], 64B rows, 4x16B chunks.
// B: [k][n128], 256B rows, 16x16B chunks.
__device__ __forceinline__ uint32_t a_swz(int m, int c) {
    return (uint32_t)(m * 64 + ((c ^ ((m >> 1) & 3)) << 4));
}
__device__ __forceinline__ uint32_t b_swz(int k, int c) {
    return (uint32_t)(k * 256 + ((c ^ (k & 7)) << 4));
}

__device__ __forceinline__ void cp_async16_s(uint32_t smem_addr, const void* g) {
    asm volatile("cp.async.ca.shared.global [%0], [%1], 16;\n"
                 :: "r"(smem_addr), "l"(g));
}
__device__ __forceinline__ void cp_commit() { asm volatile("cp.async.commit_group;\n"); }
template <int N>
__device__ __forceinline__ void cp_wait() { asm volatile("cp.async.wait_group %0;\n" :: "n"(N)); }

__device__ __forceinline__ void ldmatrix_x4(uint32_t* r, uint32_t addr) {
    asm volatile("ldmatrix.sync.aligned.m8n8.x4.shared.b16 {%0,%1,%2,%3}, [%4];"
        : "=r"(r[0]), "=r"(r[1]), "=r"(r[2]), "=r"(r[3]) : "r"(addr));
}
__device__ __forceinline__ void ldmatrix_x4_t(uint32_t* r, uint32_t addr) {
    asm volatile("ldmatrix.sync.aligned.m8n8.x4.trans.shared.b16 {%0,%1,%2,%3}, [%4];"
        : "=r"(r[0]), "=r"(r[1]), "=r"(r[2]), "=r"(r[3]) : "r"(addr));
}
__device__ __forceinline__ void mma16816(float* c, const uint32_t* a,
                                         uint32_t b0, uint32_t b1) {
    asm volatile(
        "mma.sync.aligned.m16n8k16.row.col.f32.f16.f16.f32 "
        "{%0,%1,%2,%3}, {%4,%5,%6,%7}, {%8,%9}, {%0,%1,%2,%3};"
        : "+f"(c[0]), "+f"(c[1]), "+f"(c[2]), "+f"(c[3])
        : "r"(a[0]), "r"(a[1]), "r"(a[2]), "r"(a[3]), "r"(b0), "r"(b1));
}

__global__ __launch_bounds__(128, 2)
void sbconv_mma_kernel(const int* __restrict__ sidx, float* __restrict__ out)
{
    extern __shared__ __align__(16) char smem[];
    const uint32_t smem_u = (uint32_t)__cvta_generic_to_shared(smem);

    const int tid  = threadIdx.x;
    const int lane = tid & 31;
    const int wid  = tid >> 5;
    const int wm   = wid >> 1;          // 0..1 -> m offset wm*64
    const int wn   = wid & 1;           // 0..1 -> n offset wn*64
    const int b    = blockIdx.z;
    const int d0   = blockIdx.y * BM;   // 0,128,256
    const int t0   = blockIdx.x * BN;

    const int s = __ldg(&sidx[b]);
    const __half* Wp = Wh + ((size_t)s * DPAD + d0) * CPAD;
    const __half* Xp = Xh + (size_t)b * CPAD * TLEN + t0;

    // --- cp.async staging maps ---
    // A: thread = row, 4 chunks of 16B each
    uint32_t a_dst[4];
    #pragma unroll
    for (int c = 0; c < 4; ++c) a_dst[c] = a_swz(tid, c);
    const __half* a_src = Wp + (size_t)tid * CPAD;
    // B: k = tid/4, base chunk = tid%4; 4 chunks spaced by 4
    const int bk = tid >> 2, bcb = tid & 3;
    uint32_t b_dst[4];
    #pragma unroll
    for (int j = 0; j < 4; ++j) b_dst[j] = 8192 + b_swz(bk, bcb + 4 * j);
    const __half* b_src = Xp + (size_t)bk * TLEN + bcb * 8;

    auto stage = [&](int it, int slot) {
        const uint32_t sb = smem_u + slot * STAGE_BYTES;
        const __half* as = a_src + it * BK;
        #pragma unroll
        for (int c = 0; c < 4; ++c)
            cp_async16_s(sb + a_dst[c], as + c * 8);
        const __half* bs = b_src + (size_t)it * BK * TLEN;
        #pragma unroll
        for (int j = 0; j < 4; ++j)
            cp_async16_s(sb + b_dst[j], bs + j * 32);
    };

    // --- ldmatrix lane-offset precompute ---
    uint32_t a_base[4]; int a_key[4];
    #pragma unroll
    for (int mi = 0; mi < 4; ++mi) {
        const int m = wm * 64 + mi * 16 + (lane & 15);
        a_base[mi] = (uint32_t)(m * 64);
        a_key[mi]  = (m >> 1) & 3;
    }
    const int a_chi  = lane >> 4;                 // chunk select (0/1)
    const uint32_t b_base0 = 8192u + (uint32_t)((lane & 15) * 256);
    const int b_key  = lane & 7;                  // == (lane&15)&7
    const int b_cb   = wn * 8 + (lane >> 4);

    float acc[4][8][4];
    #pragma unroll
    for (int mi = 0; mi < 4; ++mi)
        #pragma unroll
        for (int nj = 0; nj < 8; ++nj)
            #pragma unroll
            for (int q = 0; q < 4; ++q)
                acc[mi][nj][q] = 0.0f;

    // Prologue
    stage(0, 0); cp_commit();
    stage(1, 1); cp_commit();

    #pragma unroll 1
    for (int it = 0; it < NIT; ++it) {
        cp_wait<STAGES - 2>();
        __syncthreads();
        // Single barrier/iter: prefetch writes slot (it+2)%3 == (it-1)%3,
        // whose readers (iter it-1) are ordered before us by this barrier.

        if (it + 2 < NIT) stage(it + 2, (it + 2) % STAGES);
        cp_commit();

        const uint32_t sb = smem_u + (it % STAGES) * STAGE_BYTES;

        #pragma unroll
        for (int kk = 0; kk < 2; ++kk) {
            uint32_t a[4][4];
            #pragma unroll
            for (int mi = 0; mi < 4; ++mi) {
                const int chunk = kk * 2 + a_chi;
                ldmatrix_x4(a[mi], sb + a_base[mi] + ((chunk ^ a_key[mi]) << 4));
            }
            uint32_t bf[4][4];
            #pragma unroll
            for (int ni = 0; ni < 4; ++ni) {
                const int c = b_cb + ni * 2;
                ldmatrix_x4_t(bf[ni], sb + b_base0 + kk * 4096 + ((c ^ b_key) << 4));
            }
            #pragma unroll
            for (int mi = 0; mi < 4; ++mi)
                #pragma unroll
                for (int ni = 0; ni < 4; ++ni) {
                    mma16816(acc[mi][ni * 2],     a[mi], bf[ni][0], bf[ni][1]);
                    mma16816(acc[mi][ni * 2 + 1], a[mi], bf[ni][2], bf[ni][3]);
                }
        }
    }

    // --- epilogue: predicated float2 stores ---
    const int gid = lane >> 2, tig = lane & 3;
    #pragma unroll
    for (int mi = 0; mi < 4; ++mi) {
        const int m = wm * 64 + mi * 16 + gid;
        #pragma unroll
        for (int half = 0; half < 2; ++half) {
            const int d = d0 + m + half * 8;
            if (d < D1) {
                float* orow = out + ((size_t)b * D1 + d) * TLEN
                            + t0 + wn * 64 + tig * 2;
                #pragma unroll
                for (int nj = 0; nj < 8; ++nj) {
                    float2 v = make_float2(acc[mi][nj][half * 2],
                                           acc[mi][nj][half * 2 + 1]);
                    *reinterpret_cast<float2*>(orow + nj * 8) = v;
                }
            }
        }
    }
}

extern "C" void kernel_launch(void* const* d_in, const int* in_sizes, int n_in,
                              void* d_out, int out_size)
{
    const float* X    = (const float*)d_in[0];  // [B, CMAX, T]
    const int*   sidx = (const int*)  d_in[1];  // [B]
    const float* W    = (const float*)d_in[2];  // [NS, D1, CMAX]
    float*       out  = (float*)d_out;          // [B, D1, T]

    // Pass 1: fp32 -> fp16 (X once, W once, zero-padded to CPAD/DPAD)
    const int64_t total = NXV + NWV;
    const int cblocks = (int)((total + 255) / 256);
    convert_kernel<<<cblocks, 256>>>(X, W);

    // Pass 2: fp16 mma.sync GEMM
    cudaFuncSetAttribute(sbconv_mma_kernel,
                         cudaFuncAttributeMaxDynamicSharedMemorySize, SMEM_BYTES);
    dim3 grid(TLEN / BN, DPAD / BM, BATCH);  // (4, 3, 128)
    sbconv_mma_kernel<<<grid, 128, SMEM_BYTES>>>(sidx, out);
}

// round 15
// speedup vs baseline: 1.1078x; 1.1078x over previous
#include <cuda_runtime.h>
#include <cuda_fp16.h>
#include <cstdint>
#include <cstddef>

// Problem constants
constexpr int BATCH = 128;
constexpr int CMAX  = 272;
constexpr int TLEN  = 512;
constexpr int D1    = 320;
constexpr int NSUBJ = 8;
constexpr int CPAD  = 288;   // 9 * 32 channels (zero-padded)
constexpr int DPAD  = 384;   // 3 * 128 d-rows (zero-padded)

// fp16 scratch (converted once per call in a pre-pass)
__device__ __align__(16) __half Xh[(size_t)BATCH * CPAD * TLEN];  // 37.7 MB
__device__ __align__(16) __half Wh[(size_t)NSUBJ * DPAD * CPAD];  // 1.8 MB

// ---------------- pre-convert kernel ----------------
constexpr int64_t NXV = (int64_t)BATCH * CPAD * TLEN / 8;
constexpr int64_t NWV = (int64_t)NSUBJ * DPAD * CPAD / 8;

__global__ __launch_bounds__(256)
void convert_kernel(const float* __restrict__ X, const float* __restrict__ W)
{
    const int64_t i = (int64_t)blockIdx.x * blockDim.x + threadIdx.x;
    if (i < NXV) {
        const int64_t h0 = i * 8;
        const int b   = (int)(h0 / ((int64_t)CPAD * TLEN));
        const int rem = (int)(h0 % ((int64_t)CPAD * TLEN));
        const int c   = rem / TLEN;
        const int t   = rem % TLEN;
        __half2 o[4] = {};
        if (c < CMAX) {
            const float4* src = reinterpret_cast<const float4*>(
                X + ((int64_t)b * CMAX + c) * TLEN + t);
            float4 v0 = src[0], v1 = src[1];
            o[0] = __floats2half2_rn(v0.x, v0.y);
            o[1] = __floats2half2_rn(v0.z, v0.w);
            o[2] = __floats2half2_rn(v1.x, v1.y);
            o[3] = __floats2half2_rn(v1.z, v1.w);
        }
        *reinterpret_cast<uint4*>(&Xh[h0]) = *reinterpret_cast<const uint4*>(o);
    } else if (i < NXV + NWV) {
        const int64_t h0 = (i - NXV) * 8;
        const int sd = (int)(h0 / CPAD);
        const int c  = (int)(h0 % CPAD);   // multiple of 8
        const int s  = sd / DPAD;
        const int d  = sd % DPAD;
        __half2 o[4] = {};
        if (d < D1 && c < CMAX) {
            const float4* src = reinterpret_cast<const float4*>(
                W + ((int64_t)s * D1 + d) * CMAX + c);
            float4 v0 = src[0], v1 = src[1];
            o[0] = __floats2half2_rn(v0.x, v0.y);
            o[1] = __floats2half2_rn(v0.z, v0.w);
            o[2] = __floats2half2_rn(v1.x, v1.y);
            o[3] = __floats2half2_rn(v1.z, v1.w);
        }
        *reinterpret_cast<uint4*>(&Wh[h0]) = *reinterpret_cast<const uint4*>(o);
    }
}

// ------- GEMM kernel: 128x128 CTA, 8 warps of 64x32, 256 threads -------
constexpr int BM = 128;
constexpr int BN = 128;
constexpr int BK = 32;
constexpr int STAGES = 3;
constexpr int NIT = CPAD / BK;           // 9
constexpr int STAGE_BYTES = 16384;       // A 8KB + B 8KB
constexpr int SMEM_BYTES = STAGES * STAGE_BYTES;   // 49152 (static, == 48KB limit)

// Swizzled tile offsets (bytes). A: [m][k32], 64B rows, 4x16B chunks.
// B: [k][n128], 256B rows, 16x16B chunks.
__device__ __forceinline__ uint32_t a_swz(int m, int c) {
    return (uint32_t)(m * 64 + ((c ^ ((m >> 1) & 3)) << 4));
}
__device__ __forceinline__ uint32_t b_swz(int k, int c) {
    return (uint32_t)(k * 256 + ((c ^ (k & 7)) << 4));
}

__device__ __forceinline__ void cp_async16_s(uint32_t smem_addr, const void* g) {
    asm volatile("cp.async.ca.shared.global [%0], [%1], 16;\n"
                 :: "r"(smem_addr), "l"(g));
}
__device__ __forceinline__ void cp_commit() { asm volatile("cp.async.commit_group;\n"); }
template <int N>
__device__ __forceinline__ void cp_wait() { asm volatile("cp.async.wait_group %0;\n" :: "n"(N)); }

__device__ __forceinline__ void ldmatrix_x4(uint32_t* r, uint32_t addr) {
    asm volatile("ldmatrix.sync.aligned.m8n8.x4.shared.b16 {%0,%1,%2,%3}, [%4];"
        : "=r"(r[0]), "=r"(r[1]), "=r"(r[2]), "=r"(r[3]) : "r"(addr));
}
__device__ __forceinline__ void ldmatrix_x4_t(uint32_t* r, uint32_t addr) {
    asm volatile("ldmatrix.sync.aligned.m8n8.x4.trans.shared.b16 {%0,%1,%2,%3}, [%4];"
        : "=r"(r[0]), "=r"(r[1]), "=r"(r[2]), "=r"(r[3]) : "r"(addr));
}
__device__ __forceinline__ void mma16816(float* c, const uint32_t* a,
                                         uint32_t b0, uint32_t b1) {
    asm volatile(
        "mma.sync.aligned.m16n8k16.row.col.f32.f16.f16.f32 "
        "{%0,%1,%2,%3}, {%4,%5,%6,%7}, {%8,%9}, {%0,%1,%2,%3};"
        : "+f"(c[0]), "+f"(c[1]), "+f"(c[2]), "+f"(c[3])
        : "r"(a[0]), "r"(a[1]), "r"(a[2]), "r"(a[3]), "r"(b0), "r"(b1));
}

__global__ __launch_bounds__(256, 2)
void sbconv_mma_kernel(const int* __restrict__ sidx, float* __restrict__ out)
{
    __shared__ __align__(16) char smem[SMEM_BYTES];
    const uint32_t smem_u = (uint32_t)__cvta_generic_to_shared(smem);

    const int tid  = threadIdx.x;
    const int lane = tid & 31;
    const int wid  = tid >> 5;          // 0..7
    const int wm   = wid >> 2;          // 0..1 -> m offset wm*64
    const int wn   = wid & 3;           // 0..3 -> n offset wn*32
    const int b    = blockIdx.z;
    const int d0   = blockIdx.y * BM;   // 0,128,256
    const int t0   = blockIdx.x * BN;

    const int s = __ldg(&sidx[b]);
    const __half* Wp = Wh + ((size_t)s * DPAD + d0) * CPAD;
    const __half* Xp = Xh + (size_t)b * CPAD * TLEN + t0;

    // --- cp.async staging maps (256 threads, 2 chunks each per tile) ---
    // A: row = tid>>1, two consecutive 16B chunks
    const int a_row = tid >> 1;
    const int a_c0  = (tid & 1) * 2;
    uint32_t a_dst[2];
    #pragma unroll
    for (int j = 0; j < 2; ++j) a_dst[j] = a_swz(a_row, a_c0 + j);
    const __half* a_src = Wp + (size_t)a_row * CPAD + a_c0 * 8;
    // B: k = tid>>3, chunks cb and cb+8
    const int bk = tid >> 3, bcb = tid & 7;
    uint32_t b_dst[2];
    #pragma unroll
    for (int j = 0; j < 2; ++j) b_dst[j] = 8192 + b_swz(bk, bcb + 8 * j);
    const __half* b_src = Xp + (size_t)bk * TLEN + bcb * 8;

    auto stage = [&](int it, int slot) {
        const uint32_t sb = smem_u + slot * STAGE_BYTES;
        const __half* as = a_src + it * BK;
        #pragma unroll
        for (int j = 0; j < 2; ++j)
            cp_async16_s(sb + a_dst[j], as + j * 8);
        const __half* bs = b_src + (size_t)it * BK * TLEN;
        #pragma unroll
        for (int j = 0; j < 2; ++j)
            cp_async16_s(sb + b_dst[j], bs + j * 64);
    };

    // --- ldmatrix lane-offset precompute ---
    uint32_t a_base[4]; int a_key[4];
    #pragma unroll
    for (int mi = 0; mi < 4; ++mi) {
        const int m = wm * 64 + mi * 16 + (lane & 15);
        a_base[mi] = (uint32_t)(m * 64);
        a_key[mi]  = (m >> 1) & 3;
    }
    const int a_chi = lane >> 4;                  // chunk select (0/1)
    const uint32_t b_base0 = 8192u + (uint32_t)((lane & 15) * 256);
    const int b_key = lane & 7;
    const int b_cb  = wn * 4 + (lane >> 4);

    float acc[4][4][4];
    #pragma unroll
    for (int mi = 0; mi < 4; ++mi)
        #pragma unroll
        for (int nj = 0; nj < 4; ++nj)
            #pragma unroll
            for (int q = 0; q < 4; ++q)
                acc[mi][nj][q] = 0.0f;

    // Prologue
    stage(0, 0); cp_commit();
    stage(1, 1); cp_commit();

    #pragma unroll 1
    for (int it = 0; it < NIT; ++it) {
        cp_wait<STAGES - 2>();
        __syncthreads();
        // Single barrier/iter: prefetch writes slot (it+2)%3 == (it-1)%3,
        // whose readers (iter it-1) are ordered before us by this barrier.

        if (it + 2 < NIT) stage(it + 2, (it + 2) % STAGES);
        cp_commit();

        const uint32_t sb = smem_u + (it % STAGES) * STAGE_BYTES;

        #pragma unroll
        for (int kk = 0; kk < 2; ++kk) {
            uint32_t a[4][4];
            #pragma unroll
            for (int mi = 0; mi < 4; ++mi) {
                const int chunk = kk * 2 + a_chi;
                ldmatrix_x4(a[mi], sb + a_base[mi] + ((chunk ^ a_key[mi]) << 4));
            }
            uint32_t bf[2][4];
            #pragma unroll
            for (int ni = 0; ni < 2; ++ni) {
                const int c = b_cb + ni * 2;
                ldmatrix_x4_t(bf[ni], sb + b_base0 + kk * 4096 + ((c ^ b_key) << 4));
            }
            #pragma unroll
            for (int mi = 0; mi < 4; ++mi)
                #pragma unroll
                for (int ni = 0; ni < 2; ++ni) {
                    mma16816(acc[mi][ni * 2],     a[mi], bf[ni][0], bf[ni][1]);
                    mma16816(acc[mi][ni * 2 + 1], a[mi], bf[ni][2], bf[ni][3]);
                }
        }
    }

    // --- epilogue: predicated float2 stores (warp tile 64x32) ---
    const int gid = lane >> 2, tig = lane & 3;
    #pragma unroll
    for (int mi = 0; mi < 4; ++mi) {
        const int m = wm * 64 + mi * 16 + gid;
        #pragma unroll
        for (int half = 0; half < 2; ++half) {
            const int d = d0 + m + half * 8;
            if (d < D1) {
                float* orow = out + ((size_t)b * D1 + d) * TLEN
                            + t0 + wn * 32 + tig * 2;
                #pragma unroll
                for (int nj = 0; nj < 4; ++nj) {
                    float2 v = make_float2(acc[mi][nj][half * 2],
                                           acc[mi][nj][half * 2 + 1]);
                    *reinterpret_cast<float2*>(orow + nj * 8) = v;
                }
            }
        }
    }
}

extern "C" void kernel_launch(void* const* d_in, const int* in_sizes, int n_in,
                              void* d_out, int out_size)
{
    const float* X    = (const float*)d_in[0];  // [B, CMAX, T]
    const int*   sidx = (const int*)  d_in[1];  // [B]
    const float* W    = (const float*)d_in[2];  // [NS, D1, CMAX]
    float*       out  = (float*)d_out;          // [B, D1, T]

    // Pass 1: fp32 -> fp16 (X once, W once, zero-padded to CPAD/DPAD)
    const int64_t total = NXV + NWV;
    const int cblocks = (int)((total + 255) / 256);
    convert_kernel<<<cblocks, 256>>>(X, W);

    // Pass 2: fp16 mma.sync GEMM (static 48KB smem, 2 CTAs/SM)
    dim3 grid(TLEN / BN, DPAD / BM, BATCH);  // (4, 3, 128)
    sbconv_mma_kernel<<<grid, 256>>>(sidx, out);
}

// round 16
// speedup vs baseline: 1.1720x; 1.0579x over previous
#include <cuda_runtime.h>
#include <cuda_fp16.h>
#include <cstdint>
#include <cstddef>

// Problem constants
constexpr int BATCH = 128;
constexpr int CMAX  = 272;
constexpr int TLEN  = 512;
constexpr int D1    = 320;
constexpr int NSUBJ = 8;
constexpr int CPAD  = 288;   // 9 * 32 channels (zero-padded)

// fp16 scratch (converted once per call in a pre-pass)
__device__ __align__(16) __half Xh[(size_t)BATCH * CPAD * TLEN];  // 37.7 MB
__device__ __align__(16) __half Wh[(size_t)NSUBJ * D1 * CPAD];    // 1.5 MB

// ---------------- pre-convert kernel ----------------
constexpr int64_t NXV = (int64_t)BATCH * CPAD * TLEN / 8;
constexpr int64_t NWV = (int64_t)NSUBJ * D1 * CPAD / 8;

__global__ __launch_bounds__(256)
void convert_kernel(const float* __restrict__ X, const float* __restrict__ W)
{
    const int64_t i = (int64_t)blockIdx.x * blockDim.x + threadIdx.x;
    if (i < NXV) {
        const int64_t h0 = i * 8;
        const int b   = (int)(h0 / ((int64_t)CPAD * TLEN));
        const int rem = (int)(h0 % ((int64_t)CPAD * TLEN));
        const int c   = rem / TLEN;
        const int t   = rem % TLEN;
        __half2 o[4] = {};
        if (c < CMAX) {
            const float4* src = reinterpret_cast<const float4*>(
                X + ((int64_t)b * CMAX + c) * TLEN + t);
            float4 v0 = src[0], v1 = src[1];
            o[0] = __floats2half2_rn(v0.x, v0.y);
            o[1] = __floats2half2_rn(v0.z, v0.w);
            o[2] = __floats2half2_rn(v1.x, v1.y);
            o[3] = __floats2half2_rn(v1.z, v1.w);
        }
        *reinterpret_cast<uint4*>(&Xh[h0]) = *reinterpret_cast<const uint4*>(o);
    } else if (i < NXV + NWV) {
        const int64_t h0 = (i - NXV) * 8;
        const int sd = (int)(h0 / CPAD);   // s*D1 + d
        const int c  = (int)(h0 % CPAD);   // multiple of 8
        __half2 o[4] = {};
        if (c < CMAX) {
            const float4* src = reinterpret_cast<const float4*>(
                W + (int64_t)sd * CMAX + c);
            float4 v0 = src[0], v1 = src[1];
            o[0] = __floats2half2_rn(v0.x, v0.y);
            o[1] = __floats2half2_rn(v0.z, v0.w);
            o[2] = __floats2half2_rn(v1.x, v1.y);
            o[3] = __floats2half2_rn(v1.z, v1.w);
        }
        *reinterpret_cast<uint4*>(&Wh[h0]) = *reinterpret_cast<const uint4*>(o);
    }
}

// ------- GEMM kernel: 64x128 CTA, 4 warps of 32x64, 128 threads -------
constexpr int BM = 64;
constexpr int BN = 128;
constexpr int BK = 32;
constexpr int STAGES = 3;
constexpr int NIT = CPAD / BK;           // 9 (last has 16 valid k)
constexpr int A_BYTES = BM * BK * 2;     // 4096
constexpr int B_BYTES = BK * BN * 2;     // 8192
constexpr int STAGE_BYTES = A_BYTES + B_BYTES;       // 12288
constexpr int SMEM_BYTES = STAGES * STAGE_BYTES;     // 36864

// Swizzles (bytes). A: [m][k32] 64B rows, 4x16B chunks; B: [k][n128] 256B rows.
__device__ __forceinline__ uint32_t a_swz(int m, int c) {
    return (uint32_t)(m * 64 + ((c ^ ((m >> 1) & 3)) << 4));
}
__device__ __forceinline__ uint32_t b_swz(int k, int c) {
    return (uint32_t)(k * 256 + ((c ^ (k & 7)) << 4));
}

__device__ __forceinline__ void cp_async16_s(uint32_t smem_addr, const void* g) {
    asm volatile("cp.async.ca.shared.global [%0], [%1], 16;\n"
                 :: "r"(smem_addr), "l"(g));
}
__device__ __forceinline__ void cp_commit() { asm volatile("cp.async.commit_group;\n"); }
template <int N>
__device__ __forceinline__ void cp_wait() { asm volatile("cp.async.wait_group %0;\n" :: "n"(N)); }

__device__ __forceinline__ void ldmatrix_x4(uint32_t* r, uint32_t addr) {
    asm volatile("ldmatrix.sync.aligned.m8n8.x4.shared.b16 {%0,%1,%2,%3}, [%4];"
        : "=r"(r[0]), "=r"(r[1]), "=r"(r[2]), "=r"(r[3]) : "r"(addr));
}
__device__ __forceinline__ void ldmatrix_x4_t(uint32_t* r, uint32_t addr) {
    asm volatile("ldmatrix.sync.aligned.m8n8.x4.trans.shared.b16 {%0,%1,%2,%3}, [%4];"
        : "=r"(r[0]), "=r"(r[1]), "=r"(r[2]), "=r"(r[3]) : "r"(addr));
}
__device__ __forceinline__ void mma16816(float* c, const uint32_t* a,
                                         uint32_t b0, uint32_t b1) {
    asm volatile(
        "mma.sync.aligned.m16n8k16.row.col.f32.f16.f16.f32 "
        "{%0,%1,%2,%3}, {%4,%5,%6,%7}, {%8,%9}, {%0,%1,%2,%3};"
        : "+f"(c[0]), "+f"(c[1]), "+f"(c[2]), "+f"(c[3])
        : "r"(a[0]), "r"(a[1]), "r"(a[2]), "r"(a[3]), "r"(b0), "r"(b1));
}

__global__ __launch_bounds__(128, 4)
void sbconv_mma_kernel(const int* __restrict__ sidx, float* __restrict__ out)
{
    __shared__ __align__(16) char smem[SMEM_BYTES];
    const uint32_t smem_u = (uint32_t)__cvta_generic_to_shared(smem);

    const int tid  = threadIdx.x;
    const int lane = tid & 31;
    const int wid  = tid >> 5;          // 0..3
    const int wm   = wid >> 1;          // 0..1 -> m offset wm*32
    const int wn   = wid & 1;           // 0..1 -> n offset wn*64
    const int b    = blockIdx.z;
    const int d0   = blockIdx.y * BM;   // 0..256, exact
    const int t0   = blockIdx.x * BN;

    const int s = __ldg(&sidx[b]);
    const __half* Wp = Wh + ((size_t)s * D1 + d0) * CPAD;
    const __half* Xp = Xh + (size_t)b * CPAD * TLEN + t0;

    // --- cp.async staging (128 threads) ---
    // A: 4KB = 256 chunks; row = tid>>1, 2 consecutive chunks
    const int a_row = tid >> 1;
    const int a_c0  = (tid & 1) * 2;
    uint32_t a_dst[2];
    #pragma unroll
    for (int j = 0; j < 2; ++j) a_dst[j] = a_swz(a_row, a_c0 + j);
    const __half* a_src = Wp + (size_t)a_row * CPAD + a_c0 * 8;
    // B: 8KB = 512 chunks; k = tid>>2, chunks cb+4j
    const int bk = tid >> 2, bcb = tid & 3;
    uint32_t b_dst[4];
    #pragma unroll
    for (int j = 0; j < 4; ++j) b_dst[j] = A_BYTES + b_swz(bk, bcb + 4 * j);
    const __half* b_src = Xp + (size_t)bk * TLEN + bcb * 8;

    auto stage = [&](int it, int slot) {
        const uint32_t sb = smem_u + slot * STAGE_BYTES;
        const __half* as = a_src + it * BK;
        #pragma unroll
        for (int j = 0; j < 2; ++j)
            cp_async16_s(sb + a_dst[j], as + j * 8);
        const __half* bs = b_src + (size_t)it * BK * TLEN;
        #pragma unroll
        for (int j = 0; j < 4; ++j)
            cp_async16_s(sb + b_dst[j], bs + j * 32);
    };

    // --- ldmatrix lane-offset precompute ---
    uint32_t a_base[2]; int a_key[2];
    #pragma unroll
    for (int mi = 0; mi < 2; ++mi) {
        const int m = wm * 32 + mi * 16 + (lane & 15);
        a_base[mi] = (uint32_t)(m * 64);
        a_key[mi]  = (m >> 1) & 3;
    }
    const int a_chi = lane >> 4;                  // 0/1
    const uint32_t b_base0 = (uint32_t)A_BYTES + (uint32_t)((lane & 15) * 256);
    const int b_key = lane & 7;
    const int b_cb  = wn * 8 + (lane >> 4);

    float acc[2][8][4];
    #pragma unroll
    for (int mi = 0; mi < 2; ++mi)
        #pragma unroll
        for (int nj = 0; nj < 8; ++nj)
            #pragma unroll
            for (int q = 0; q < 4; ++q)
                acc[mi][nj][q] = 0.0f;

    // One kk16 step of compute on stage base sb
    auto compute_kk = [&](uint32_t sb, int kk) {
        uint32_t a[2][4];
        #pragma unroll
        for (int mi = 0; mi < 2; ++mi) {
            const int chunk = kk * 2 + a_chi;
            ldmatrix_x4(a[mi], sb + a_base[mi] + ((chunk ^ a_key[mi]) << 4));
        }
        uint32_t bf[4][4];
        #pragma unroll
        for (int ni = 0; ni < 4; ++ni) {
            const int c = b_cb + ni * 2;
            ldmatrix_x4_t(bf[ni], sb + b_base0 + kk * 4096 + ((c ^ b_key) << 4));
        }
        #pragma unroll
        for (int mi = 0; mi < 2; ++mi)
            #pragma unroll
            for (int ni = 0; ni < 4; ++ni) {
                mma16816(acc[mi][ni * 2],     a[mi], bf[ni][0], bf[ni][1]);
                mma16816(acc[mi][ni * 2 + 1], a[mi], bf[ni][2], bf[ni][3]);
            }
    };

    // Prologue
    stage(0, 0); cp_commit();
    stage(1, 1); cp_commit();

    #pragma unroll 1
    for (int it = 0; it < NIT - 1; ++it) {
        cp_wait<STAGES - 2>();
        __syncthreads();
        // Single barrier/iter: prefetch writes slot (it+2)%3 == (it-1)%3,
        // whose readers (iter it-1) are ordered before us by this barrier.
        if (it + 2 < NIT) stage(it + 2, (it + 2) % STAGES);
        cp_commit();

        const uint32_t sb = smem_u + (it % STAGES) * STAGE_BYTES;
        compute_kk(sb, 0);
        compute_kk(sb, 1);
    }
    // Tail iteration (it = NIT-1): channels 256..271 valid, 272..287 are
    // zero-padded -> kk=1 half contributes nothing; skip its MMAs.
    {
        cp_wait<0>();
        __syncthreads();
        const uint32_t sb = smem_u + ((NIT - 1) % STAGES) * STAGE_BYTES;
        compute_kk(sb, 0);
    }

    // --- epilogue: float2 stores, no predicates (exact tiling) ---
    const int gid = lane >> 2, tig = lane & 3;
    #pragma unroll
    for (int mi = 0; mi < 2; ++mi) {
        const int m = wm * 32 + mi * 16 + gid;
        #pragma unroll
        for (int half = 0; half < 2; ++half) {
            const int d = d0 + m + half * 8;
            float* orow = out + ((size_t)b * D1 + d) * TLEN
                        + t0 + wn * 64 + tig * 2;
            #pragma unroll
            for (int nj = 0; nj < 8; ++nj) {
                float2 v = make_float2(acc[mi][nj][half * 2],
                                       acc[mi][nj][half * 2 + 1]);
                *reinterpret_cast<float2*>(orow + nj * 8) = v;
            }
        }
    }
}

extern "C" void kernel_launch(void* const* d_in, const int* in_sizes, int n_in,
                              void* d_out, int out_size)
{
    const float* X    = (const float*)d_in[0];  // [B, CMAX, T]
    const int*   sidx = (const int*)  d_in[1];  // [B]
    const float* W    = (const float*)d_in[2];  // [NS, D1, CMAX]
    float*       out  = (float*)d_out;          // [B, D1, T]

    // Pass 1: fp32 -> fp16 (X once, W once, zero-padded to CPAD)
    const int64_t total = NXV + NWV;
    const int cblocks = (int)((total + 255) / 256);
    convert_kernel<<<cblocks, 256>>>(X, W);

    // Pass 2: fp16 mma.sync GEMM (static 36KB smem, 4 CTAs/SM)
    dim3 grid(TLEN / BN, D1 / BM, BATCH);  // (4, 5, 128)
    sbconv_mma_kernel<<<grid, 128>>>(sidx, out);
}